// round 16
// baseline (speedup 1.0000x reference)
#include <cuda_runtime.h>
#include <cuda_fp16.h>
#include <math.h>

#define BATCH 4
#define CH    128
#define N_    4096
#define EPSV  2.220446049250313e-16f
#define SCALE2 144.26950408889634f   // 100 * log2(e)

// ---------------------------------------------------------------------------
// Device scratch
// ---------------------------------------------------------------------------
__device__ float g_xbar[2 * BATCH * CH];
__device__ uint4 g_Qpk[BATCH * 32 * 4096];        // Q A-frags: [0,2048) hi, [2048,4096) lo per blk
__device__ uint4 g_Kpk[BATCH * 64 * 2048];        // K B-frags (b0h,b1h,b0l,b1l) per 64-key blk
__device__ uint2 g_Vpk[BATCH * 64 * 2048];        // V B-frags hi-only (vh01,vh89) per blk

__device__ __forceinline__ void mma_f16(float c[4],
                                        unsigned int a0, unsigned int a1,
                                        unsigned int a2, unsigned int a3,
                                        unsigned int b0, unsigned int b1) {
    asm volatile("mma.sync.aligned.m16n8k16.row.col.f32.f16.f16.f32 "
                 "{%0,%1,%2,%3}, {%4,%5,%6,%7}, {%8,%9}, {%0,%1,%2,%3};\n"
                 : "+f"(c[0]), "+f"(c[1]), "+f"(c[2]), "+f"(c[3])
                 : "r"(a0), "r"(a1), "r"(a2), "r"(a3), "r"(b0), "r"(b1));
}

__device__ __forceinline__ unsigned int h2u(__half2 h) {
    return *reinterpret_cast<unsigned int*>(&h);
}

__device__ __forceinline__ unsigned int pack_hi(float a, float b) {
    return h2u(__halves2half2(__float2half_rn(a), __float2half_rn(b)));
}
// lo residual of f16 split
__device__ __forceinline__ unsigned int pack_lo(float a, float b) {
    __half ha = __float2half_rn(a), hb = __float2half_rn(b);
    return h2u(__halves2half2(__float2half_rn(a - __half2float(ha)),
                              __float2half_rn(b - __half2float(hb))));
}

__device__ __forceinline__ void cpasync16(void* s, const void* g) {
    unsigned int saddr = (unsigned int)__cvta_generic_to_shared(s);
    asm volatile("cp.async.cg.shared.global [%0], [%1], 16;\n" :: "r"(saddr), "l"(g));
}

// ---------------------------------------------------------------------------
// K0: spatial means
// ---------------------------------------------------------------------------
__global__ void k_means(const float* __restrict__ m_in, const float* __restrict__ rs) {
    int row   = blockIdx.x;
    int which = row >> 9;
    int bc    = row & 511;
    const float* src = which ? m_in : rs;
    const float* p = src + (size_t)bc * N_;

    float s = 0.f;
    for (int i = threadIdx.x; i < N_; i += 256) s += p[i];

    __shared__ float sh[256];
    sh[threadIdx.x] = s;
    __syncthreads();
    for (int off = 128; off > 0; off >>= 1) {
        if (threadIdx.x < off) sh[threadIdx.x] += sh[threadIdx.x + off];
        __syncthreads();
    }
    if (threadIdx.x == 0) g_xbar[which * 512 + bc] = sh[0] * (1.0f / N_);
}

// ---------------------------------------------------------------------------
// K1: projection + mean-center + L2-normalize + DIRECT fragment emission.
// which=0: theta (from rs) -> K B-frags.  which=1: phi (from m) -> Q A-frags.
// Block covers 16 spatial positions = exactly one Q mt-tile row / two K nt-tiles.
// ---------------------------------------------------------------------------
__global__ void k_proj(const float* __restrict__ m_in, const float* __restrict__ rs,
                       const float* __restrict__ theta_w, const float* __restrict__ phi_w) {
    int tile  = blockIdx.x;           // 0..255
    int b     = blockIdx.y;
    int which = blockIdx.z;
    const float* X = which ? m_in : rs;
    const float* W = which ? phi_w : theta_w;
    const float* xbar = &g_xbar[which * 512 + b * CH];

    int o  = threadIdx.x;
    int n0 = tile * 16;

    __shared__ float Ws[128 * 33];
    __shared__ float xs[32 * 16];
    __shared__ float sq[128 * 17];
    __shared__ float val[128 * 17];   // staged normalized outputs [c][j]

    float acc[16];
#pragma unroll
    for (int j = 0; j < 16; j++) acc[j] = 0.f;

    for (int c0 = 0; c0 < CH; c0 += 32) {
        for (int i = threadIdx.x; i < 128 * 32; i += 128) {
            int oo = i >> 5, cc = i & 31;
            Ws[oo * 33 + cc] = W[oo * CH + c0 + cc];
        }
        for (int i = threadIdx.x; i < 32 * 16; i += 128) {
            int cc = i >> 4;
            int j  = i & 15;
            int c  = c0 + cc;
            xs[i] = X[((size_t)(b * CH + c)) * N_ + n0 + j] - xbar[c];
        }
        __syncthreads();
#pragma unroll 8
        for (int cc = 0; cc < 32; cc++) {
            float w = Ws[o * 33 + cc];
#pragma unroll
            for (int j = 0; j < 16; j++) acc[j] += w * xs[cc * 16 + j];
        }
        __syncthreads();
    }

#pragma unroll
    for (int j = 0; j < 16; j++) sq[o * 17 + j] = acc[j] * acc[j];
    for (int off = 64; off > 0; off >>= 1) {
        __syncthreads();
        if (o < off) {
#pragma unroll
            for (int j = 0; j < 16; j++) sq[o * 17 + j] += sq[(o + off) * 17 + j];
        }
    }
    __syncthreads();

#pragma unroll
    for (int j = 0; j < 16; j++) {
        float norm = sqrtf(sq[j]) + EPSV;
        val[o * 17 + j] = acc[j] / norm;
    }
    __syncthreads();

    if (which) {
        // ---- phi -> Q A-frags: blk = tile>>3, wt = tile&7 ----
        int blk = tile >> 3, wt = tile & 7;
        uint4* dst = g_Qpk + ((size_t)(b * 32 + blk)) * 4096;
        for (int idx = threadIdx.x; idx < 256; idx += 128) {
            int ks = idx >> 5, lane = idx & 31;
            int g = lane >> 2, l = lane & 3;
            int c0 = 16 * ks + 2 * l;
            float q00 = val[c0 * 17 + g],           q01 = val[(c0 + 1) * 17 + g];
            float q10 = val[c0 * 17 + g + 8],       q11 = val[(c0 + 1) * 17 + g + 8];
            float q20 = val[(c0 + 8) * 17 + g],     q21 = val[(c0 + 9) * 17 + g];
            float q30 = val[(c0 + 8) * 17 + g + 8], q31 = val[(c0 + 9) * 17 + g + 8];
            uint4 hi, lo;
            hi.x = pack_hi(q00, q01); lo.x = pack_lo(q00, q01);
            hi.y = pack_hi(q10, q11); lo.y = pack_lo(q10, q11);
            hi.z = pack_hi(q20, q21); lo.z = pack_lo(q20, q21);
            hi.w = pack_hi(q30, q31); lo.w = pack_lo(q30, q31);
            int oidx = (ks * 8 + wt) * 32 + lane;
            dst[oidx] = hi;
            dst[2048 + oidx] = lo;
        }
    } else {
        // ---- theta -> K B-frags: kb = tile>>2, nt = (tile&3)*2 + nt2 ----
        int kb = tile >> 2, ch4 = tile & 3;
        uint4* dst = g_Kpk + ((size_t)(b * 64 + kb)) * 2048;
        for (int idx = threadIdx.x; idx < 512; idx += 128) {
            int ks = idx >> 6, rem = idx & 63;
            int nt2 = rem >> 5, lane = rem & 31;
            int g = lane >> 2, l = lane & 3;
            int m = 8 * nt2 + g;              // local key 0..15
            int c0 = 16 * ks + 2 * l;
            float k00 = val[c0 * 17 + m],       k01 = val[(c0 + 1) * 17 + m];
            float k10 = val[(c0 + 8) * 17 + m], k11 = val[(c0 + 9) * 17 + m];
            uint4 outv;
            outv.x = pack_hi(k00, k01);
            outv.y = pack_hi(k10, k11);
            outv.z = pack_lo(k00, k01);
            outv.w = pack_lo(k10, k11);
            int nt = ch4 * 2 + nt2;
            dst[(ks * 8 + nt) * 32 + lane] = outv;
        }
    }
}

// ---------------------------------------------------------------------------
// Pack V (rs) into m16n8k16 B-frag order, f16 hi only (uint2 per frag).
// ---------------------------------------------------------------------------
__global__ void k_packV(const float* __restrict__ rs) {
    __shared__ float Vt[128 * 68];
    int kb = blockIdx.x, b = blockIdx.y;
    int m0 = kb * 64;

    for (int i = threadIdx.x; i < 2048; i += 256) {
        int c = i >> 4, mq = (i & 15) << 2;
        float4 v = *(const float4*)(rs + ((size_t)(b * CH + c)) * N_ + m0 + mq);
        *(float4*)(Vt + c * 68 + mq) = v;
    }
    __syncthreads();

    uint2* dst = g_Vpk + ((size_t)(b * 64 + kb)) * 2048;
    for (int o = threadIdx.x; o < 2048; o += 256) {
        int lane = o & 31, ct = (o >> 5) & 15, kt = o >> 9;
        int g = lane >> 2, l = lane & 3;
        int c = 8 * ct + g;
        int m = 16 * kt + 2 * l;
        uint2 outv;
        outv.x = pack_hi(Vt[c * 68 + m],     Vt[c * 68 + m + 1]);
        outv.y = pack_hi(Vt[c * 68 + m + 8], Vt[c * 68 + m + 9]);
        dst[o] = outv;
    }
}

// ---------------------------------------------------------------------------
// K2: flash attention v9. 512 threads = 16 warps.
// Warp w: wt = w&7 owns rows 16wt..+15; grp = w>>3 owns keys [32*grp, +32).
// S: 3x f16 m16n8k16 (hi/lo). PV: 1x f16 m16n8k16 (Ph*Vh).
// Alpha-rescale skipped when tile doesn't raise the row max (alpha == 1).
// ---------------------------------------------------------------------------
#define BUF_FLOATS 12288

__global__ void __launch_bounds__(512, 1)
k_attn(float* __restrict__ out) {
    extern __shared__ float sm[];
    uint4* Qf = (uint4*)sm;                  // 4096 uint4: [0,2048) hi, [2048,4096) lo

    int b    = blockIdx.y;
    int n0   = blockIdx.x << 7;
    int tid  = threadIdx.x;
    int lane = tid & 31, w = tid >> 5;
    int wt = w & 7, grp = w >> 3;
    int ntb = grp << 2;                      // nt base
    int g = lane >> 2, l = lane & 3;

    // load persistent Q fragments
    {
        const uint4* qsrc = g_Qpk + ((size_t)(b * 32 + blockIdx.x)) * 4096;
        for (int i = tid; i < 4096; i += 512) Qf[i] = qsrc[i];
    }

    // prologue: async load tile 0 into buffer 0
    {
        uint4* kd = (uint4*)(sm + 16384);
        const uint4* ksrc = g_Kpk + ((size_t)(b * 64 + 0)) * 2048;
        for (int i = tid; i < 2048; i += 512) cpasync16(kd + i, ksrc + i);
        uint4* vd = (uint4*)(sm + 16384 + 8192);
        const uint4* vsrc = (const uint4*)(g_Vpk + ((size_t)(b * 64 + 0)) * 2048);
        for (int i = tid; i < 1024; i += 512) cpasync16(vd + i, vsrc + i);
        asm volatile("cp.async.commit_group;\n" ::);
    }

    float O[16][4];
#pragma unroll
    for (int ct = 0; ct < 16; ct++)
#pragma unroll
        for (int j = 0; j < 4; j++) O[ct][j] = 0.f;
    float mi[2] = {-INFINITY, -INFINITY};
    float li[2] = {0.f, 0.f};

    for (int kb = 0; kb < 64; kb++) {
        int cur = kb & 1;
        uint4* Kbuf = (uint4*)(sm + 16384 + cur * BUF_FLOATS);
        uint2* Vbuf = (uint2*)(sm + 16384 + cur * BUF_FLOATS + 8192);

        if (kb < 63) {
            uint4* kd = (uint4*)(sm + 16384 + (1 - cur) * BUF_FLOATS);
            const uint4* ksrc = g_Kpk + ((size_t)(b * 64 + kb + 1)) * 2048;
            for (int i = tid; i < 2048; i += 512) cpasync16(kd + i, ksrc + i);
            uint4* vd = (uint4*)(sm + 16384 + (1 - cur) * BUF_FLOATS + 8192);
            const uint4* vsrc = (const uint4*)(g_Vpk + ((size_t)(b * 64 + kb + 1)) * 2048);
            for (int i = tid; i < 1024; i += 512) cpasync16(vd + i, vsrc + i);
            asm volatile("cp.async.commit_group;\n" ::);
            asm volatile("cp.async.wait_group 1;\n" ::);
        } else {
            asm volatile("cp.async.wait_group 0;\n" ::);
        }
        __syncthreads();

        // ---- S = Q^T K over this group's 32 keys : 3x f16 mma ----
        float S[4][4];
#pragma unroll
        for (int nt = 0; nt < 4; nt++)
#pragma unroll
            for (int j = 0; j < 4; j++) S[nt][j] = 0.f;

#pragma unroll
        for (int ks = 0; ks < 8; ks++) {
            int qi = (ks * 8 + wt) * 32 + lane;
            uint4 qh = Qf[qi];
            uint4 ql = Qf[2048 + qi];
#pragma unroll
            for (int nt4 = 0; nt4 < 4; nt4++) {
                uint4 kf = Kbuf[(ks * 8 + ntb + nt4) * 32 + lane];
                mma_f16(S[nt4], qh.x, qh.y, qh.z, qh.w, kf.x, kf.y);
                mma_f16(S[nt4], ql.x, ql.y, ql.z, ql.w, kf.x, kf.y);
                mma_f16(S[nt4], qh.x, qh.y, qh.z, qh.w, kf.z, kf.w);
            }
        }

        // ---- warp-local online softmax over 32 keys; P overwrites S ----
#pragma unroll
        for (int hb = 0; hb < 2; hb++) {
            float vmax = -INFINITY;
#pragma unroll
            for (int nt = 0; nt < 4; nt++)
                vmax = fmaxf(vmax, fmaxf(S[nt][2 * hb], S[nt][2 * hb + 1]));
            vmax = fmaxf(vmax, __shfl_xor_sync(0xffffffffu, vmax, 1));
            vmax = fmaxf(vmax, __shfl_xor_sync(0xffffffffu, vmax, 2));
            float mnew  = fmaxf(mi[hb], vmax);
            float alpha = exp2f((mi[hb] - mnew) * SCALE2);
            mi[hb] = mnew;

            float rs_ = 0.f;
#pragma unroll
            for (int nt = 0; nt < 4; nt++) {
                float p0 = exp2f((S[nt][2 * hb]     - mnew) * SCALE2);
                float p1 = exp2f((S[nt][2 * hb + 1] - mnew) * SCALE2);
                S[nt][2 * hb]     = p0;
                S[nt][2 * hb + 1] = p1;
                rs_ += p0 + p1;
            }
            rs_ += __shfl_xor_sync(0xffffffffu, rs_, 1);
            rs_ += __shfl_xor_sync(0xffffffffu, rs_, 2);
            li[hb] = li[hb] * alpha + rs_;

            if (alpha < 1.0f) {   // skip O-rescale once the row max is stable
#pragma unroll
                for (int ct = 0; ct < 16; ct++) {
                    O[ct][2 * hb]     *= alpha;
                    O[ct][2 * hb + 1] *= alpha;
                }
            }
        }

        // ---- PV over this group's 2 kt blocks : 1x f16 mma (Ph*Vh) ----
#pragma unroll
        for (int kt2 = 0; kt2 < 2; kt2++) {
            unsigned int Pha[4];
#pragma unroll
            for (int hf2 = 0; hf2 < 2; hf2++) {
                int nt = 2 * kt2 + hf2;
#pragma unroll
                for (int hb = 0; hb < 2; hb++)
                    Pha[hf2 * 2 + hb] = pack_hi(S[nt][2 * hb], S[nt][2 * hb + 1]);
            }
            int kt = 2 * grp + kt2;
#pragma unroll
            for (int ct = 0; ct < 16; ct++) {
                uint2 vf = Vbuf[(kt * 16 + ct) * 32 + lane];
                mma_f16(O[ct], Pha[0], Pha[1], Pha[2], Pha[3], vf.x, vf.y);
            }
        }
        __syncthreads();
    }

    // ---- cross-group flash merge via smem (aliases buffers) ----
    float* MG = sm + 16384;   // 68 * 512 floats
    if (grp == 1) {
        int slot = tid - 256;
#pragma unroll
        for (int ct = 0; ct < 16; ct++)
#pragma unroll
            for (int j = 0; j < 4; j++)
                MG[(ct * 4 + j) * 512 + slot] = O[ct][j];
#pragma unroll
        for (int hb = 0; hb < 2; hb++) {
            MG[(64 + hb) * 512 + slot] = mi[hb];
            MG[(66 + hb) * 512 + slot] = li[hb];
        }
    }
    __syncthreads();

    if (grp == 0) {
        float* yout = out;
        float* loc  = out + (size_t)BATCH * CH * N_;
#pragma unroll
        for (int hb = 0; hb < 2; hb++) {
            float m1 = MG[(64 + hb) * 512 + tid];
            float l1 = MG[(66 + hb) * 512 + tid];
            float m  = fmaxf(mi[hb], m1);
            float a0 = exp2f((mi[hb] - m) * SCALE2);
            float a1 = exp2f((m1 - m) * SCALE2);
            float lt = li[hb] * a0 + l1 * a1;
            float inv = 1.0f / lt;
            float sc  = m * inv;
            int   r   = n0 + 16 * wt + g + 8 * hb;
#pragma unroll
            for (int ct = 0; ct < 16; ct++) {
                float o0 = O[ct][2 * hb]     * a0 + MG[(ct * 4 + 2 * hb) * 512 + tid]     * a1;
                float o1 = O[ct][2 * hb + 1] * a0 + MG[(ct * 4 + 2 * hb + 1) * 512 + tid] * a1;
                int c0 = 8 * ct + 2 * l;
                yout[((size_t)(b * CH + c0)) * N_ + r]     = o0 * sc;
                yout[((size_t)(b * CH + c0 + 1)) * N_ + r] = o1 * sc;
            }
            if (l == 0) loc[(size_t)b * N_ + r] = inv;
        }
    }
}

// ---------------------------------------------------------------------------
extern "C" void kernel_launch(void* const* d_in, const int* in_sizes, int n_in,
                              void* d_out, int out_size) {
    const float* m_in = (const float*)d_in[0];
    const float* rs   = (const float*)d_in[1];
    const float* thw  = (const float*)d_in[2];
    const float* phw  = (const float*)d_in[4];
    float* out = (float*)d_out;

    k_means<<<1024, 256>>>(m_in, rs);
    k_proj<<<dim3(N_ / 16, BATCH, 2), 128>>>(m_in, rs, thw, phw);
    k_packV<<<dim3(64, BATCH), 256>>>(rs);

    size_t smem = (size_t)51200 * sizeof(float);   // 200 KB (merge region aliases buffers)
    cudaFuncSetAttribute(k_attn, cudaFuncAttributeMaxDynamicSharedMemorySize, (int)smem);
    k_attn<<<dim3(N_ / 128, BATCH), 512, smem>>>(out);
}

// round 17
// speedup vs baseline: 1.0021x; 1.0021x over previous
#include <cuda_runtime.h>
#include <cuda_fp16.h>
#include <math.h>

#define BATCH 4
#define CH    128
#define N_    4096
#define EPSV  2.220446049250313e-16f
#define SCALE2 144.26950408889634f   // 100 * log2(e)

// ---------------------------------------------------------------------------
// Device scratch
// ---------------------------------------------------------------------------
__device__ float g_xbar[2 * BATCH * CH];
__device__ uint4 g_Qpk[BATCH * 32 * 4096];        // Q A-frags: [0,2048) hi, [2048,4096) lo per blk
__device__ uint4 g_Kpk[BATCH * 64 * 2048];        // K B-frags (b0h,b1h,b0l,b1l) per 64-key blk
__device__ uint2 g_Vpk[BATCH * 64 * 2048];        // V B-frags hi-only (vh01,vh89) per blk

__device__ __forceinline__ void mma_f16(float c[4],
                                        unsigned int a0, unsigned int a1,
                                        unsigned int a2, unsigned int a3,
                                        unsigned int b0, unsigned int b1) {
    asm volatile("mma.sync.aligned.m16n8k16.row.col.f32.f16.f16.f32 "
                 "{%0,%1,%2,%3}, {%4,%5,%6,%7}, {%8,%9}, {%0,%1,%2,%3};\n"
                 : "+f"(c[0]), "+f"(c[1]), "+f"(c[2]), "+f"(c[3])
                 : "r"(a0), "r"(a1), "r"(a2), "r"(a3), "r"(b0), "r"(b1));
}

__device__ __forceinline__ unsigned int h2u(__half2 h) {
    return *reinterpret_cast<unsigned int*>(&h);
}

__device__ __forceinline__ unsigned int pack_hi(float a, float b) {
    return h2u(__halves2half2(__float2half_rn(a), __float2half_rn(b)));
}
// lo residual of f16 split
__device__ __forceinline__ unsigned int pack_lo(float a, float b) {
    __half ha = __float2half_rn(a), hb = __float2half_rn(b);
    return h2u(__halves2half2(__float2half_rn(a - __half2float(ha)),
                              __float2half_rn(b - __half2float(hb))));
}

__device__ __forceinline__ void cpasync16(void* s, const void* g) {
    unsigned int saddr = (unsigned int)__cvta_generic_to_shared(s);
    asm volatile("cp.async.cg.shared.global [%0], [%1], 16;\n" :: "r"(saddr), "l"(g));
}

// ---------------------------------------------------------------------------
// K0: spatial means (float4 vectorized)
// ---------------------------------------------------------------------------
__global__ void k_means(const float* __restrict__ m_in, const float* __restrict__ rs) {
    int row   = blockIdx.x;
    int which = row >> 9;
    int bc    = row & 511;
    const float* src = which ? m_in : rs;
    const float4* p4 = (const float4*)(src + (size_t)bc * N_);

    float s = 0.f;
    for (int i = threadIdx.x; i < N_ / 4; i += 256) {
        float4 v = p4[i];
        s += (v.x + v.y) + (v.z + v.w);
    }

    __shared__ float sh[256];
    sh[threadIdx.x] = s;
    __syncthreads();
    for (int off = 128; off > 0; off >>= 1) {
        if (threadIdx.x < off) sh[threadIdx.x] += sh[threadIdx.x + off];
        __syncthreads();
    }
    if (threadIdx.x == 0) g_xbar[which * 512 + bc] = sh[0] * (1.0f / N_);
}

// ---------------------------------------------------------------------------
// K1: projection + center + L2-normalize + direct fragment emission, v2.
// Block covers 64 spatial positions; 256 threads = (o = tid&127, h = tid>>7).
// which=0: theta -> K B-frags (block = one complete 64-key frag block).
// which=1: phi   -> Q A-frags (block = 4 mt tiles of one 128-row blk).
// Dynamic smem layout (floats): Ws[0,4224) xs[4224,6400) B[6400,15104) nrm[15104,15168)
// ---------------------------------------------------------------------------
__global__ void k_proj(const float* __restrict__ m_in, const float* __restrict__ rs,
                       const float* __restrict__ theta_w, const float* __restrict__ phi_w) {
    extern __shared__ float ps[];
    float* Ws  = ps;            // [o][cc] stride 33
    float* xs  = ps + 4224;     // [cc][j] stride 68
    float* B   = ps + 6400;     // [c][j]  stride 68 (sq partials, then values)
    float* nrm = ps + 15104;    // [64] inverse norms

    int blk64 = blockIdx.x;     // 0..63
    int b     = blockIdx.y;
    int which = blockIdx.z;
    const float* X = which ? m_in : rs;
    const float* W = which ? phi_w : theta_w;
    const float* xbar = &g_xbar[which * 512 + b * CH];

    int tid = threadIdx.x;
    int o = tid & 127, h = tid >> 7;
    int j0 = h * 32;
    int n0 = blk64 * 64;

    float acc[32];
#pragma unroll
    for (int j = 0; j < 32; j++) acc[j] = 0.f;

    for (int c0 = 0; c0 < CH; c0 += 32) {
        for (int i = tid; i < 128 * 32; i += 256) {
            int oo = i >> 5, cc = i & 31;
            Ws[oo * 33 + cc] = W[oo * CH + c0 + cc];
        }
        for (int i = tid; i < 32 * 64; i += 256) {
            int cc = i >> 6, j = i & 63;
            xs[cc * 68 + j] = X[((size_t)(b * CH + c0 + cc)) * N_ + n0 + j] - xbar[c0 + cc];
        }
        __syncthreads();
#pragma unroll 4
        for (int cc = 0; cc < 32; cc++) {
            float w = Ws[o * 33 + cc];
            const float* xr = xs + cc * 68 + j0;
#pragma unroll
            for (int j = 0; j < 32; j++) acc[j] += w * xr[j];
        }
        __syncthreads();
    }

    // column sum-of-squares reduction over channels
#pragma unroll
    for (int j = 0; j < 32; j++) B[o * 68 + j0 + j] = acc[j] * acc[j];
    for (int off = 64; off > 0; off >>= 1) {
        __syncthreads();
        if (o < off) {
#pragma unroll
            for (int j = 0; j < 32; j++)
                B[o * 68 + j0 + j] += B[(o + off) * 68 + j0 + j];
        }
    }
    __syncthreads();
    if (o == 0) {
#pragma unroll
        for (int j = 0; j < 32; j++)
            nrm[j0 + j] = 1.0f / (sqrtf(B[j0 + j]) + EPSV);
    }
    __syncthreads();

    // write normalized values into B as [c][j]
#pragma unroll
    for (int j = 0; j < 32; j++) B[o * 68 + j0 + j] = acc[j] * nrm[j0 + j];
    __syncthreads();

    if (which) {
        // ---- phi -> Q A-frags: blk = blk64>>1, tiles wt0..wt0+3 ----
        int blk = blk64 >> 1, wt0 = (blk64 & 1) * 4;
        uint4* dst = g_Qpk + ((size_t)(b * 32 + blk)) * 4096;
        for (int idx = tid; idx < 1024; idx += 256) {
            int ks = idx >> 7, jt = (idx >> 5) & 3, lane = idx & 31;
            int g = lane >> 2, l = lane & 3;
            int r = jt * 16 + g;              // local row 0..63
            int c0 = 16 * ks + 2 * l;
            float q00 = B[c0 * 68 + r],           q01 = B[(c0 + 1) * 68 + r];
            float q10 = B[c0 * 68 + r + 8],       q11 = B[(c0 + 1) * 68 + r + 8];
            float q20 = B[(c0 + 8) * 68 + r],     q21 = B[(c0 + 9) * 68 + r];
            float q30 = B[(c0 + 8) * 68 + r + 8], q31 = B[(c0 + 9) * 68 + r + 8];
            uint4 hi, lo;
            hi.x = pack_hi(q00, q01); lo.x = pack_lo(q00, q01);
            hi.y = pack_hi(q10, q11); lo.y = pack_lo(q10, q11);
            hi.z = pack_hi(q20, q21); lo.z = pack_lo(q20, q21);
            hi.w = pack_hi(q30, q31); lo.w = pack_lo(q30, q31);
            int oidx = (ks * 8 + wt0 + jt) * 32 + lane;
            dst[oidx] = hi;
            dst[2048 + oidx] = lo;
        }
    } else {
        // ---- theta -> K B-frags: kb = blk64 (full 64-key block) ----
        uint4* dst = g_Kpk + ((size_t)(b * 64 + blk64)) * 2048;
        for (int idx = tid; idx < 2048; idx += 256) {
            int ks = idx >> 8, nt = (idx >> 5) & 7, lane = idx & 31;
            int g = lane >> 2, l = lane & 3;
            int m = 8 * nt + g;               // local key 0..63
            int c0 = 16 * ks + 2 * l;
            float k00 = B[c0 * 68 + m],       k01 = B[(c0 + 1) * 68 + m];
            float k10 = B[(c0 + 8) * 68 + m], k11 = B[(c0 + 9) * 68 + m];
            uint4 outv;
            outv.x = pack_hi(k00, k01);
            outv.y = pack_hi(k10, k11);
            outv.z = pack_lo(k00, k01);
            outv.w = pack_lo(k10, k11);
            dst[(ks * 8 + nt) * 32 + lane] = outv;
        }
    }
}

// ---------------------------------------------------------------------------
// Pack V (rs) into m16n8k16 B-frag order, f16 hi only (uint2 per frag).
// ---------------------------------------------------------------------------
__global__ void k_packV(const float* __restrict__ rs) {
    __shared__ float Vt[128 * 68];
    int kb = blockIdx.x, b = blockIdx.y;
    int m0 = kb * 64;

    for (int i = threadIdx.x; i < 2048; i += 256) {
        int c = i >> 4, mq = (i & 15) << 2;
        float4 v = *(const float4*)(rs + ((size_t)(b * CH + c)) * N_ + m0 + mq);
        *(float4*)(Vt + c * 68 + mq) = v;
    }
    __syncthreads();

    uint2* dst = g_Vpk + ((size_t)(b * 64 + kb)) * 2048;
    for (int o = threadIdx.x; o < 2048; o += 256) {
        int lane = o & 31, ct = (o >> 5) & 15, kt = o >> 9;
        int g = lane >> 2, l = lane & 3;
        int c = 8 * ct + g;
        int m = 16 * kt + 2 * l;
        uint2 outv;
        outv.x = pack_hi(Vt[c * 68 + m],     Vt[c * 68 + m + 1]);
        outv.y = pack_hi(Vt[c * 68 + m + 8], Vt[c * 68 + m + 9]);
        dst[o] = outv;
    }
}

// ---------------------------------------------------------------------------
// K2: flash attention v9 (unchanged numerics). 512 threads = 16 warps.
// S: 3x f16 m16n8k16 (hi/lo). PV: 1x f16 m16n8k16 (Ph*Vh). Alpha-skip.
// ---------------------------------------------------------------------------
#define BUF_FLOATS 12288

__global__ void __launch_bounds__(512, 1)
k_attn(float* __restrict__ out) {
    extern __shared__ float sm[];
    uint4* Qf = (uint4*)sm;                  // 4096 uint4: [0,2048) hi, [2048,4096) lo

    int b    = blockIdx.y;
    int n0   = blockIdx.x << 7;
    int tid  = threadIdx.x;
    int lane = tid & 31, w = tid >> 5;
    int wt = w & 7, grp = w >> 3;
    int ntb = grp << 2;                      // nt base
    int g = lane >> 2, l = lane & 3;

    // load persistent Q fragments
    {
        const uint4* qsrc = g_Qpk + ((size_t)(b * 32 + blockIdx.x)) * 4096;
        for (int i = tid; i < 4096; i += 512) Qf[i] = qsrc[i];
    }

    // prologue: async load tile 0 into buffer 0
    {
        uint4* kd = (uint4*)(sm + 16384);
        const uint4* ksrc = g_Kpk + ((size_t)(b * 64 + 0)) * 2048;
        for (int i = tid; i < 2048; i += 512) cpasync16(kd + i, ksrc + i);
        uint4* vd = (uint4*)(sm + 16384 + 8192);
        const uint4* vsrc = (const uint4*)(g_Vpk + ((size_t)(b * 64 + 0)) * 2048);
        for (int i = tid; i < 1024; i += 512) cpasync16(vd + i, vsrc + i);
        asm volatile("cp.async.commit_group;\n" ::);
    }

    float O[16][4];
#pragma unroll
    for (int ct = 0; ct < 16; ct++)
#pragma unroll
        for (int j = 0; j < 4; j++) O[ct][j] = 0.f;
    float mi[2] = {-INFINITY, -INFINITY};
    float li[2] = {0.f, 0.f};

    for (int kb = 0; kb < 64; kb++) {
        int cur = kb & 1;
        uint4* Kbuf = (uint4*)(sm + 16384 + cur * BUF_FLOATS);
        uint2* Vbuf = (uint2*)(sm + 16384 + cur * BUF_FLOATS + 8192);

        if (kb < 63) {
            uint4* kd = (uint4*)(sm + 16384 + (1 - cur) * BUF_FLOATS);
            const uint4* ksrc = g_Kpk + ((size_t)(b * 64 + kb + 1)) * 2048;
            for (int i = tid; i < 2048; i += 512) cpasync16(kd + i, ksrc + i);
            uint4* vd = (uint4*)(sm + 16384 + (1 - cur) * BUF_FLOATS + 8192);
            const uint4* vsrc = (const uint4*)(g_Vpk + ((size_t)(b * 64 + kb + 1)) * 2048);
            for (int i = tid; i < 1024; i += 512) cpasync16(vd + i, vsrc + i);
            asm volatile("cp.async.commit_group;\n" ::);
            asm volatile("cp.async.wait_group 1;\n" ::);
        } else {
            asm volatile("cp.async.wait_group 0;\n" ::);
        }
        __syncthreads();

        // ---- S = Q^T K over this group's 32 keys : 3x f16 mma ----
        float S[4][4];
#pragma unroll
        for (int nt = 0; nt < 4; nt++)
#pragma unroll
            for (int j = 0; j < 4; j++) S[nt][j] = 0.f;

#pragma unroll
        for (int ks = 0; ks < 8; ks++) {
            int qi = (ks * 8 + wt) * 32 + lane;
            uint4 qh = Qf[qi];
            uint4 ql = Qf[2048 + qi];
#pragma unroll
            for (int nt4 = 0; nt4 < 4; nt4++) {
                uint4 kf = Kbuf[(ks * 8 + ntb + nt4) * 32 + lane];
                mma_f16(S[nt4], qh.x, qh.y, qh.z, qh.w, kf.x, kf.y);
                mma_f16(S[nt4], ql.x, ql.y, ql.z, ql.w, kf.x, kf.y);
                mma_f16(S[nt4], qh.x, qh.y, qh.z, qh.w, kf.z, kf.w);
            }
        }

        // ---- warp-local online softmax over 32 keys; P overwrites S ----
#pragma unroll
        for (int hb = 0; hb < 2; hb++) {
            float vmax = -INFINITY;
#pragma unroll
            for (int nt = 0; nt < 4; nt++)
                vmax = fmaxf(vmax, fmaxf(S[nt][2 * hb], S[nt][2 * hb + 1]));
            vmax = fmaxf(vmax, __shfl_xor_sync(0xffffffffu, vmax, 1));
            vmax = fmaxf(vmax, __shfl_xor_sync(0xffffffffu, vmax, 2));
            float mnew  = fmaxf(mi[hb], vmax);
            float alpha = exp2f((mi[hb] - mnew) * SCALE2);
            mi[hb] = mnew;

            float rs_ = 0.f;
#pragma unroll
            for (int nt = 0; nt < 4; nt++) {
                float p0 = exp2f((S[nt][2 * hb]     - mnew) * SCALE2);
                float p1 = exp2f((S[nt][2 * hb + 1] - mnew) * SCALE2);
                S[nt][2 * hb]     = p0;
                S[nt][2 * hb + 1] = p1;
                rs_ += p0 + p1;
            }
            rs_ += __shfl_xor_sync(0xffffffffu, rs_, 1);
            rs_ += __shfl_xor_sync(0xffffffffu, rs_, 2);
            li[hb] = li[hb] * alpha + rs_;

            if (alpha < 1.0f) {   // skip O-rescale once the row max is stable
#pragma unroll
                for (int ct = 0; ct < 16; ct++) {
                    O[ct][2 * hb]     *= alpha;
                    O[ct][2 * hb + 1] *= alpha;
                }
            }
        }

        // ---- PV over this group's 2 kt blocks : 1x f16 mma (Ph*Vh) ----
#pragma unroll
        for (int kt2 = 0; kt2 < 2; kt2++) {
            unsigned int Pha[4];
#pragma unroll
            for (int hf2 = 0; hf2 < 2; hf2++) {
                int nt = 2 * kt2 + hf2;
#pragma unroll
                for (int hb = 0; hb < 2; hb++)
                    Pha[hf2 * 2 + hb] = pack_hi(S[nt][2 * hb], S[nt][2 * hb + 1]);
            }
            int kt = 2 * grp + kt2;
#pragma unroll
            for (int ct = 0; ct < 16; ct++) {
                uint2 vf = Vbuf[(kt * 16 + ct) * 32 + lane];
                mma_f16(O[ct], Pha[0], Pha[1], Pha[2], Pha[3], vf.x, vf.y);
            }
        }
        __syncthreads();
    }

    // ---- cross-group flash merge via smem (aliases buffers) ----
    float* MG = sm + 16384;   // 68 * 512 floats
    if (grp == 1) {
        int slot = tid - 256;
#pragma unroll
        for (int ct = 0; ct < 16; ct++)
#pragma unroll
            for (int j = 0; j < 4; j++)
                MG[(ct * 4 + j) * 512 + slot] = O[ct][j];
#pragma unroll
        for (int hb = 0; hb < 2; hb++) {
            MG[(64 + hb) * 512 + slot] = mi[hb];
            MG[(66 + hb) * 512 + slot] = li[hb];
        }
    }
    __syncthreads();

    if (grp == 0) {
        float* yout = out;
        float* loc  = out + (size_t)BATCH * CH * N_;
#pragma unroll
        for (int hb = 0; hb < 2; hb++) {
            float m1 = MG[(64 + hb) * 512 + tid];
            float l1 = MG[(66 + hb) * 512 + tid];
            float m  = fmaxf(mi[hb], m1);
            float a0 = exp2f((mi[hb] - m) * SCALE2);
            float a1 = exp2f((m1 - m) * SCALE2);
            float lt = li[hb] * a0 + l1 * a1;
            float inv = 1.0f / lt;
            float sc  = m * inv;
            int   r   = n0 + 16 * wt + g + 8 * hb;
#pragma unroll
            for (int ct = 0; ct < 16; ct++) {
                float o0 = O[ct][2 * hb]     * a0 + MG[(ct * 4 + 2 * hb) * 512 + tid]     * a1;
                float o1 = O[ct][2 * hb + 1] * a0 + MG[(ct * 4 + 2 * hb + 1) * 512 + tid] * a1;
                int c0 = 8 * ct + 2 * l;
                yout[((size_t)(b * CH + c0)) * N_ + r]     = o0 * sc;
                yout[((size_t)(b * CH + c0 + 1)) * N_ + r] = o1 * sc;
            }
            if (l == 0) loc[(size_t)b * N_ + r] = inv;
        }
    }
}

// ---------------------------------------------------------------------------
extern "C" void kernel_launch(void* const* d_in, const int* in_sizes, int n_in,
                              void* d_out, int out_size) {
    const float* m_in = (const float*)d_in[0];
    const float* rs   = (const float*)d_in[1];
    const float* thw  = (const float*)d_in[2];
    const float* phw  = (const float*)d_in[4];
    float* out = (float*)d_out;

    k_means<<<1024, 256>>>(m_in, rs);
    cudaFuncSetAttribute(k_proj, cudaFuncAttributeMaxDynamicSharedMemorySize, 15168 * 4);
    k_proj<<<dim3(N_ / 64, BATCH, 2), 256, 15168 * 4>>>(m_in, rs, thw, phw);
    k_packV<<<dim3(64, BATCH), 256>>>(rs);

    size_t smem = (size_t)51200 * sizeof(float);   // 200 KB (merge region aliases buffers)
    cudaFuncSetAttribute(k_attn, cudaFuncAttributeMaxDynamicSharedMemorySize, (int)smem);
    k_attn<<<dim3(N_ / 128, BATCH), 512, smem>>>(out);
}